// round 9
// baseline (speedup 1.0000x reference)
#include <cuda_runtime.h>
#include <cstdint>

// Problem constants
#define BS    8
#define NN    2048
#define DIN   256
#define HH    128
#define ALPHA 0.2f

// Scratch (device globals: no allocation allowed)
__device__ float g_ht[BS * HH * NN];   // 8 MB: h^T [b][c][n], tf32-rounded
__device__ float g_ss[BS * NN];        // s_self
__device__ float g_sn[BS * NN];        // s_nb

static __device__ __forceinline__ uint32_t smem_u32(const void* p) {
    uint32_t r;
    asm("{ .reg .u64 t; cvta.to.shared.u64 t, %1; cvt.u32.u64 %0, t; }"
        : "=r"(r) : "l"(p));
    return r;
}

static __device__ __forceinline__ uint32_t tf32rn(float x) {
    uint32_t r;
    asm("cvt.rna.tf32.f32 %0, %1;" : "=r"(r) : "f"(x));
    return r;
}

#define CP_ASYNC16(dst_u32, src_ptr) \
    asm volatile("cp.async.cg.shared.global [%0], [%1], 16;" \
                 :: "r"(dst_u32), "l"(src_ptr) : "memory")
#define CP_COMMIT()  asm volatile("cp.async.commit_group;" ::: "memory")
#define CP_WAIT(n)   asm volatile("cp.async.wait_group %0;" :: "n"(n) : "memory")

#define BAR_SYNC(id, cnt) \
    asm volatile("bar.sync %0, %1;" :: "r"(id), "r"(cnt) : "memory")
#define BAR_ARRIVE(id, cnt) \
    asm volatile("bar.arrive %0, %1;" :: "r"(id), "r"(cnt) : "memory")

// Named barrier ids
#define FULL0 1   // 1,2,3 : stage full  (producers arrive, consumers sync)
#define FREE0 4   // 4,5,6 : stage free  (consumers arrive, producers sync)
#define PBAR  7   // producers-only

// D += A(16x8 row-major) * B(8x8 col-major), tf32 in, fp32 accum
static __device__ __forceinline__ void mma_tf32(float* c, uint32_t a0, uint32_t a1,
                                                uint32_t a2, uint32_t a3,
                                                uint32_t b0, uint32_t b1) {
    asm volatile(
        "mma.sync.aligned.m16n8k8.row.col.f32.tf32.tf32.f32 "
        "{%0,%1,%2,%3}, {%4,%5,%6,%7}, {%8,%9}, {%0,%1,%2,%3};"
        : "+f"(c[0]), "+f"(c[1]), "+f"(c[2]), "+f"(c[3])
        : "r"(a0), "r"(a1), "r"(a2), "r"(a3), "r"(b0), "r"(b1));
}

#define PAD  36  // B row stride (floats)
#define PADA 40  // A row stride (floats): LDS.64-friendly, conflict-free

// ============================================================================
// Kernel 1: h = x @ W^T on tf32 mma. CTA: 128 n-rows x 128 c-cols, K=256.
// Epilogue: scatter tf32(h) to g_ht (transposed) + fused ss/sn dots.
// ============================================================================
__global__ __launch_bounds__(256) void k1_hgemm(const float* __restrict__ x,
                                                const float* __restrict__ W,
                                                const float* __restrict__ a) {
    __shared__ uint32_t sA[128][PAD];   // x tile  [n][d]
    __shared__ uint32_t sB[128][PAD];   // W tile  [c][d]
    __shared__ float sh_ps[2][128];
    __shared__ float sh_pn[2][128];

    const int b    = blockIdx.y;
    const int row0 = blockIdx.x * 128;
    const int tid  = threadIdx.x;
    const int lane = tid & 31;
    const int gr   = lane >> 2;
    const int kq   = lane & 3;
    const int warp_m = (tid >> 5) & 3;
    const int warp_n = tid >> 7;

    float acc[2][8][4];
#pragma unroll
    for (int mt = 0; mt < 2; mt++)
#pragma unroll
        for (int nt = 0; nt < 8; nt++)
#pragma unroll
            for (int q = 0; q < 4; q++) acc[mt][nt][q] = 0.f;

    const float* xb = x + ((size_t)b * NN + row0) * DIN;

    for (int d0 = 0; d0 < DIN; d0 += 32) {
        __syncthreads();
#pragma unroll
        for (int p = 0; p < 4; p++) {
            int flat = p * 256 + tid;   // 0..1023
            int row  = flat >> 3;
            int q8   = flat & 7;
            float4 xv = *(const float4*)(xb + (size_t)row * DIN + d0 + q8 * 4);
            uint4 u;
            u.x = tf32rn(xv.x); u.y = tf32rn(xv.y);
            u.z = tf32rn(xv.z); u.w = tf32rn(xv.w);
            *(uint4*)&sA[row][q8 * 4] = u;
            float4 wv = *(const float4*)(W + (size_t)row * DIN + d0 + q8 * 4);
            u.x = tf32rn(wv.x); u.y = tf32rn(wv.y);
            u.z = tf32rn(wv.z); u.w = tf32rn(wv.w);
            *(uint4*)&sB[row][q8 * 4] = u;
        }
        __syncthreads();

#pragma unroll
        for (int k0 = 0; k0 < 32; k0 += 8) {
            uint32_t afrag[2][4];
#pragma unroll
            for (int mt = 0; mt < 2; mt++) {
                int i = warp_m * 32 + mt * 16 + gr;
                afrag[mt][0] = sA[i][k0 + kq];
                afrag[mt][1] = sA[i + 8][k0 + kq];
                afrag[mt][2] = sA[i][k0 + kq + 4];
                afrag[mt][3] = sA[i + 8][k0 + kq + 4];
            }
            uint32_t bfrag[8][2];
#pragma unroll
            for (int nt = 0; nt < 8; nt++) {
                int n = warp_n * 64 + nt * 8 + gr;
                bfrag[nt][0] = sB[n][k0 + kq];
                bfrag[nt][1] = sB[n][k0 + kq + 4];
            }
#pragma unroll
            for (int mt = 0; mt < 2; mt++)
#pragma unroll
                for (int nt = 0; nt < 8; nt++)
                    mma_tf32(acc[mt][nt], afrag[mt][0], afrag[mt][1],
                             afrag[mt][2], afrag[mt][3],
                             bfrag[nt][0], bfrag[nt][1]);
        }
    }

    // ---- epilogue: scatter h^T (tf32-rounded) + ss/sn partial dots ----
    float* htb = g_ht + (size_t)b * HH * NN;
    float psA[2] = {0.f, 0.f}, pnA[2] = {0.f, 0.f};
    float psB[2] = {0.f, 0.f}, pnB[2] = {0.f, 0.f};
#pragma unroll
    for (int mt = 0; mt < 2; mt++) {
        int nA = row0 + warp_m * 32 + mt * 16 + gr;
        int nB = nA + 8;
#pragma unroll
        for (int nt = 0; nt < 8; nt++) {
            int c0 = warp_n * 64 + nt * 8 + kq * 2;
            float as0 = a[c0], as1 = a[c0 + 1];
            float an0 = a[HH + c0], an1 = a[HH + c0 + 1];
            float v0 = acc[mt][nt][0], v1 = acc[mt][nt][1];
            float v2 = acc[mt][nt][2], v3 = acc[mt][nt][3];
            psA[mt] += v0 * as0 + v1 * as1;
            pnA[mt] += v0 * an0 + v1 * an1;
            psB[mt] += v2 * as0 + v3 * as1;
            pnB[mt] += v2 * an0 + v3 * an1;
            htb[(size_t)c0 * NN + nA]       = __uint_as_float(tf32rn(v0));
            htb[(size_t)(c0 + 1) * NN + nA] = __uint_as_float(tf32rn(v1));
            htb[(size_t)c0 * NN + nB]       = __uint_as_float(tf32rn(v2));
            htb[(size_t)(c0 + 1) * NN + nB] = __uint_as_float(tf32rn(v3));
        }
    }
#pragma unroll
    for (int o = 1; o <= 2; o <<= 1) {
#pragma unroll
        for (int mt = 0; mt < 2; mt++) {
            psA[mt] += __shfl_xor_sync(0xffffffffu, psA[mt], o);
            pnA[mt] += __shfl_xor_sync(0xffffffffu, pnA[mt], o);
            psB[mt] += __shfl_xor_sync(0xffffffffu, psB[mt], o);
            pnB[mt] += __shfl_xor_sync(0xffffffffu, pnB[mt], o);
        }
    }
    if (kq == 0) {
#pragma unroll
        for (int mt = 0; mt < 2; mt++) {
            int rA = warp_m * 32 + mt * 16 + gr;
            sh_ps[warp_n][rA]     = psA[mt];
            sh_pn[warp_n][rA]     = pnA[mt];
            sh_ps[warp_n][rA + 8] = psB[mt];
            sh_pn[warp_n][rA + 8] = pnB[mt];
        }
    }
    __syncthreads();
    if (tid < 128) {
        g_ss[b * NN + row0 + tid] = sh_ps[0][tid] + sh_ps[1][tid];
        g_sn[b * NN + row0 + tid] = sh_pn[0][tid] + sh_pn[1][tid];
    }
}

// ============================================================================
// Kernel 3: warp-specialized masked-softmax aggregation (tf32 mma.sync).
// 768 threads: warps 0-15 consumers (each M32xN32), warps 16-23 producers
// (cp.async adj/B, factored-exp w-gen into k-permuted A, denominators).
// Triple-buffered stages; A layout permuted so consumer A frags are LDS.64.
// ============================================================================
#define K3_CH 64   // chunks of 32 over K=2048
#define ST    3    // stages
#define STA_BYTES (128*PADA*4)   // 20480 (A, permuted, PAD 40)
#define STB_BYTES (128*PAD*4)    // 18432 (B, PAD 36)
#define ADJ_BYTES (128*32*4)     // 16384
// dynamic smem layout (bytes)
#define OFF_SA   0
#define OFF_SB   (OFF_SA + ST*STA_BYTES)
#define OFF_ADJ  (OFF_SB + ST*STB_BYTES)
#define OFF_F    (OFF_ADJ + ST*ADJ_BYTES)    // f32[2048]
#define OFF_H    (OFF_F + 2048*4)            // f32[2048]
#define OFF_EG   (OFF_H + 2048*4)            // float2[128]
#define OFF_DEN  (OFF_EG + 128*8)            // f32[128]
#define K3_SMEM  (OFF_DEN + 128*4)

__global__ __launch_bounds__(768, 1) void k3_attn(const float* __restrict__ adj,
                                                  float* __restrict__ out) {
    extern __shared__ char dsm[];
    const uint32_t smb = smem_u32(dsm);

    uint32_t* smA   = (uint32_t*)(dsm + OFF_SA);
    uint32_t* smB   = (uint32_t*)(dsm + OFF_SB);
    float*    smAdj = (float*)(dsm + OFF_ADJ);
    float*    shF   = (float*)(dsm + OFF_F);
    float*    shH   = (float*)(dsm + OFF_H);
    float2*   shEG  = (float2*)(dsm + OFF_EG);
    float*    shDen = (float*)(dsm + OFF_DEN);

    const int b    = blockIdx.y;
    const int i0   = blockIdx.x * 128;
    const int tid  = threadIdx.x;
    const int wid  = tid >> 5;
    const int lane = tid & 31;

    const float* adjb = adj + ((size_t)b * NN + i0) * NN;
    const float* htb  = g_ht + (size_t)b * HH * NN;

    // ---- producer cp.async mapping (256 producer threads) ----
    const int ptid = tid & 255;
    const int cq   = ptid & 7;
    int crow[4];
#pragma unroll
    for (int p = 0; p < 4; p++) crow[p] = (p * 256 + ptid) >> 3;

    // ---- producer prologue: issue chunks 0,1 before tables ----
    if (wid >= 16) {
#pragma unroll
        for (int c0 = 0; c0 < 2; c0++) {
#pragma unroll
            for (int p = 0; p < 4; p++) {
                int r = crow[p];
                CP_ASYNC16(smb + OFF_ADJ + c0 * ADJ_BYTES + (r * 32 + cq * 4) * 4,
                           adjb + (size_t)r * NN + c0 * 32 + cq * 4);
                CP_ASYNC16(smb + OFF_SB + c0 * STB_BYTES + (r * PAD + cq * 4) * 4,
                           htb + (size_t)r * NN + c0 * 32 + cq * 4);
            }
            CP_COMMIT();
        }
    }

    // ---- tables (all 768 threads) ----
    for (int j = tid; j < NN; j += 768) {
        float sn = g_sn[b * NN + j];
        shF[j] = expf(sn);
        shH[j] = expf(0.2f * sn);
    }
    if (tid < 128) {
        float ss = g_ss[b * NN + i0 + tid];
        shEG[tid] = make_float2(expf(ss), expf(0.2f * ss));
    }
    __syncthreads();

    if (wid >= 16) {
        // ================= PRODUCER (8 warps) =================
        const int pw = wid - 16;         // 0..7, rows pw*16..+15
        // permuted store column: pairs (k, k+4) adjacent for consumer LDS.64
        const int permlane = ((lane >> 3) << 3) + ((lane & 3) << 1) + ((lane >> 2) & 1);
        float den[16];
#pragma unroll
        for (int q = 0; q < 16; q++) den[q] = 0.f;

        for (int g = 0; g < K3_CH; g++) {
            const int s = g % ST;
            if (g < K3_CH - 1) CP_WAIT(1); else CP_WAIT(0);
            BAR_SYNC(PBAR, 256);        // chunk g adj+B visible to producers

            // gen w tile into sA[s] (permuted layout)
            {
                float F = shF[g * 32 + lane];
                float H = shH[g * 32 + lane];
                float*    adjS = smAdj + s * (128 * 32);
                uint32_t* aS   = smA + s * (128 * PADA) + permlane;
#pragma unroll
                for (int ii = 0; ii < 16; ii++) {
                    int    r  = pw * 16 + ii;
                    float  av = adjS[r * 32 + lane];
                    float2 eg = shEG[r];
                    float  pp = eg.x * F;
                    float  w  = av * ((pp >= 1.f) ? pp : eg.y * H);
                    uint32_t wr = tf32rn(w);
                    den[ii] += __uint_as_float(wr);
                    aS[r * PADA] = wr;
                }
            }
            BAR_ARRIVE(FULL0 + s, 768);

            // prefetch chunk g+2 into stage (g+2)%ST
            if (g + 2 < K3_CH) {
                const int s2 = (g + 2) % ST;
                if (g >= 1) BAR_SYNC(FREE0 + s2, 768);  // consumer g-1 done
                const int j2 = (g + 2) * 32;
#pragma unroll
                for (int p = 0; p < 4; p++) {
                    int r = crow[p];
                    CP_ASYNC16(smb + OFF_ADJ + s2 * ADJ_BYTES + (r * 32 + cq * 4) * 4,
                               adjb + (size_t)r * NN + j2 + cq * 4);
                    CP_ASYNC16(smb + OFF_SB + s2 * STB_BYTES + (r * PAD + cq * 4) * 4,
                               htb + (size_t)r * NN + j2 + cq * 4);
                }
                CP_COMMIT();
            }
        }

        // denominators -> shDen
#pragma unroll
        for (int ii = 0; ii < 16; ii++) {
            float v = den[ii];
#pragma unroll
            for (int o = 16; o; o >>= 1) v += __shfl_xor_sync(0xffffffffu, v, o);
            if (lane == 0) shDen[pw * 16 + ii] = v;
        }
        __syncthreads();
        // producers done
    } else {
        // ================= CONSUMER (16 warps, each M32 x N32) =================
        const int gr     = lane >> 2;
        const int kq     = lane & 3;
        const int warp_m = wid & 3;    // M block of 32
        const int warp_n = wid >> 2;   // N block of 32

        float acc[2][4][4];
#pragma unroll
        for (int mt = 0; mt < 2; mt++)
#pragma unroll
            for (int nt = 0; nt < 4; nt++)
#pragma unroll
                for (int q = 0; q < 4; q++) acc[mt][nt][q] = 0.f;

        for (int t = 0; t < K3_CH; t++) {
            const int s = t % ST;
            BAR_SYNC(FULL0 + s, 768);
            const uint32_t* sAb = smA + s * (128 * PADA);
            const uint32_t* sBb = smB + s * (128 * PAD);
#pragma unroll
            for (int k0 = 0; k0 < 32; k0 += 8) {
                // A frags via LDS.64 on permuted layout: (k0+kq, k0+kq+4)
                uint2 a_lo[2], a_hi[2];
#pragma unroll
                for (int mt = 0; mt < 2; mt++) {
                    int i = warp_m * 32 + mt * 16 + gr;
                    a_lo[mt] = *(const uint2*)&sAb[i * PADA + k0 + kq * 2];
                    a_hi[mt] = *(const uint2*)&sAb[(i + 8) * PADA + k0 + kq * 2];
                }
                uint32_t bfrag[4][2];
#pragma unroll
                for (int nt = 0; nt < 4; nt++) {
                    int n = warp_n * 32 + nt * 8 + gr;
                    bfrag[nt][0] = sBb[n * PAD + k0 + kq];
                    bfrag[nt][1] = sBb[n * PAD + k0 + kq + 4];
                }
#pragma unroll
                for (int mt = 0; mt < 2; mt++)
#pragma unroll
                    for (int nt = 0; nt < 4; nt++)
                        mma_tf32(acc[mt][nt], a_lo[mt].x, a_hi[mt].x,
                                 a_lo[mt].y, a_hi[mt].y,
                                 bfrag[nt][0], bfrag[nt][1]);
            }
            if (t < K3_CH - ST) BAR_ARRIVE(FREE0 + s, 768);
        }
        __syncthreads();  // shDen ready

        // ---- epilogue: normalize, ELU, store ----
#pragma unroll
        for (int mt = 0; mt < 2; mt++) {
            int   rA   = warp_m * 32 + mt * 16 + gr;
            int   rB   = rA + 8;
            float invA = 1.f / shDen[rA];
            float invB = 1.f / shDen[rB];
            float* oA  = out + ((size_t)(b * NN + i0 + rA)) * HH + warp_n * 32;
            float* oB  = out + ((size_t)(b * NN + i0 + rB)) * HH + warp_n * 32;
#pragma unroll
            for (int nt = 0; nt < 4; nt++) {
                float v0 = acc[mt][nt][0] * invA;
                float v1 = acc[mt][nt][1] * invA;
                float v2 = acc[mt][nt][2] * invB;
                float v3 = acc[mt][nt][3] * invB;
                float2 pA, pB;
                pA.x = (v0 > 0.f) ? v0 : expm1f(v0);
                pA.y = (v1 > 0.f) ? v1 : expm1f(v1);
                pB.x = (v2 > 0.f) ? v2 : expm1f(v2);
                pB.y = (v3 > 0.f) ? v3 : expm1f(v3);
                *(float2*)&oA[nt * 8 + kq * 2] = pA;
                *(float2*)&oB[nt * 8 + kq * 2] = pB;
            }
        }
    }
}

// ============================================================================
// Launch
// ============================================================================
extern "C" void kernel_launch(void* const* d_in, const int* in_sizes, int n_in,
                              void* d_out, int out_size) {
    const float* x   = (const float*)d_in[0];  // [8, 2048, 256]
    const float* adj = (const float*)d_in[1];  // [8, 2048, 2048]
    const float* W   = (const float*)d_in[2];  // [128, 256]
    const float* a   = (const float*)d_in[3];  // [256]
    float*       out = (float*)d_out;          // [8, 2048, 128]

    cudaFuncSetAttribute(k3_attn, cudaFuncAttributeMaxDynamicSharedMemorySize,
                         K3_SMEM);

    k1_hgemm<<<dim3(NN / 128, BS), 256>>>(x, W, a);
    k3_attn<<<dim3(NN / 128, BS), 768, K3_SMEM>>>(adj, out);
}

// round 10
// speedup vs baseline: 1.0698x; 1.0698x over previous
#include <cuda_runtime.h>
#include <cstdint>

// Problem constants
#define BS    8
#define NN    2048
#define DIN   256
#define HH    128
#define ALPHA 0.2f

// Scratch (device globals: no allocation allowed)
// g_ht column index j is PERMUTED within each 8-group: jj -> ((jj&3)<<1)|(jj>>2)
__device__ float g_ht[BS * HH * NN];
__device__ float g_ss[BS * NN];
__device__ float g_sn[BS * NN];

static __device__ __forceinline__ uint32_t smem_u32(const void* p) {
    uint32_t r;
    asm("{ .reg .u64 t; cvta.to.shared.u64 t, %1; cvt.u32.u64 %0, t; }"
        : "=r"(r) : "l"(p));
    return r;
}

static __device__ __forceinline__ uint32_t tf32rn(float x) {
    uint32_t r;
    asm("cvt.rna.tf32.f32 %0, %1;" : "=r"(r) : "f"(x));
    return r;
}

#define CP_ASYNC16(dst_u32, src_ptr) \
    asm volatile("cp.async.cg.shared.global [%0], [%1], 16;" \
                 :: "r"(dst_u32), "l"(src_ptr) : "memory")
#define CP_COMMIT()  asm volatile("cp.async.commit_group;" ::: "memory")
#define CP_WAIT(n)   asm volatile("cp.async.wait_group %0;" :: "n"(n) : "memory")

#define BAR_SYNC(id, cnt) \
    asm volatile("bar.sync %0, %1;" :: "r"(id), "r"(cnt) : "memory")
#define BAR_ARRIVE(id, cnt) \
    asm volatile("bar.arrive %0, %1;" :: "r"(id), "r"(cnt) : "memory")

// Named barrier ids
#define FULL0 1   // 1,2,3 : stage full  (producers arrive, consumers sync)
#define FREE0 4   // 4,5,6 : stage free  (consumers arrive, producers sync)
#define PBAR  7   // producers-only

// D += A(16x8 row-major) * B(8x8 col-major), tf32 in, fp32 accum
static __device__ __forceinline__ void mma_tf32(float* c, uint32_t a0, uint32_t a1,
                                                uint32_t a2, uint32_t a3,
                                                uint32_t b0, uint32_t b1) {
    asm volatile(
        "mma.sync.aligned.m16n8k8.row.col.f32.tf32.tf32.f32 "
        "{%0,%1,%2,%3}, {%4,%5,%6,%7}, {%8,%9}, {%0,%1,%2,%3};"
        : "+f"(c[0]), "+f"(c[1]), "+f"(c[2]), "+f"(c[3])
        : "r"(a0), "r"(a1), "r"(a2), "r"(a3), "r"(b0), "r"(b1));
}

#define PAD  36  // k1 tile row stride
#define PADK 40  // k3 A/B row stride: conflict-free LDS.64 (banks gr*8+kq*2)

// ============================================================================
// Kernel 1: h = x @ W^T on tf32 mma. CTA: 128 n-rows x 128 c-cols, K=256.
// Epilogue: scatter tf32(h) to g_ht with PERMUTED j (for k3 LDS.64 B frags)
// + fused ss/sn dots.
// ============================================================================
__global__ __launch_bounds__(256) void k1_hgemm(const float* __restrict__ x,
                                                const float* __restrict__ W,
                                                const float* __restrict__ a) {
    __shared__ uint32_t sA[128][PAD];
    __shared__ uint32_t sB[128][PAD];
    __shared__ float sh_ps[2][128];
    __shared__ float sh_pn[2][128];

    const int b    = blockIdx.y;
    const int row0 = blockIdx.x * 128;
    const int tid  = threadIdx.x;
    const int lane = tid & 31;
    const int gr   = lane >> 2;
    const int kq   = lane & 3;
    const int warp_m = (tid >> 5) & 3;
    const int warp_n = tid >> 7;

    float acc[2][8][4];
#pragma unroll
    for (int mt = 0; mt < 2; mt++)
#pragma unroll
        for (int nt = 0; nt < 8; nt++)
#pragma unroll
            for (int q = 0; q < 4; q++) acc[mt][nt][q] = 0.f;

    const float* xb = x + ((size_t)b * NN + row0) * DIN;

    for (int d0 = 0; d0 < DIN; d0 += 32) {
        __syncthreads();
#pragma unroll
        for (int p = 0; p < 4; p++) {
            int flat = p * 256 + tid;
            int row  = flat >> 3;
            int q8   = flat & 7;
            float4 xv = *(const float4*)(xb + (size_t)row * DIN + d0 + q8 * 4);
            uint4 u;
            u.x = tf32rn(xv.x); u.y = tf32rn(xv.y);
            u.z = tf32rn(xv.z); u.w = tf32rn(xv.w);
            *(uint4*)&sA[row][q8 * 4] = u;
            float4 wv = *(const float4*)(W + (size_t)row * DIN + d0 + q8 * 4);
            u.x = tf32rn(wv.x); u.y = tf32rn(wv.y);
            u.z = tf32rn(wv.z); u.w = tf32rn(wv.w);
            *(uint4*)&sB[row][q8 * 4] = u;
        }
        __syncthreads();

#pragma unroll
        for (int k0 = 0; k0 < 32; k0 += 8) {
            uint32_t afrag[2][4];
#pragma unroll
            for (int mt = 0; mt < 2; mt++) {
                int i = warp_m * 32 + mt * 16 + gr;
                afrag[mt][0] = sA[i][k0 + kq];
                afrag[mt][1] = sA[i + 8][k0 + kq];
                afrag[mt][2] = sA[i][k0 + kq + 4];
                afrag[mt][3] = sA[i + 8][k0 + kq + 4];
            }
            uint32_t bfrag[8][2];
#pragma unroll
            for (int nt = 0; nt < 8; nt++) {
                int n = warp_n * 64 + nt * 8 + gr;
                bfrag[nt][0] = sB[n][k0 + kq];
                bfrag[nt][1] = sB[n][k0 + kq + 4];
            }
#pragma unroll
            for (int mt = 0; mt < 2; mt++)
#pragma unroll
                for (int nt = 0; nt < 8; nt++)
                    mma_tf32(acc[mt][nt], afrag[mt][0], afrag[mt][1],
                             afrag[mt][2], afrag[mt][3],
                             bfrag[nt][0], bfrag[nt][1]);
        }
    }

    // ---- epilogue: scatter h^T (tf32, j-permuted) + ss/sn dots ----
    // permuted column for row n (low 3 bits): ((gr&3)<<1)|(gr>>2)
    const int grp = ((gr & 3) << 1) | (gr >> 2);
    float* htb = g_ht + (size_t)b * HH * NN;
    float psA[2] = {0.f, 0.f}, pnA[2] = {0.f, 0.f};
    float psB[2] = {0.f, 0.f}, pnB[2] = {0.f, 0.f};
#pragma unroll
    for (int mt = 0; mt < 2; mt++) {
        int nA = row0 + warp_m * 32 + mt * 16 + grp;   // permuted position
        int nB = nA + 8;
#pragma unroll
        for (int nt = 0; nt < 8; nt++) {
            int c0 = warp_n * 64 + nt * 8 + kq * 2;
            float as0 = a[c0], as1 = a[c0 + 1];
            float an0 = a[HH + c0], an1 = a[HH + c0 + 1];
            float v0 = acc[mt][nt][0], v1 = acc[mt][nt][1];
            float v2 = acc[mt][nt][2], v3 = acc[mt][nt][3];
            psA[mt] += v0 * as0 + v1 * as1;
            pnA[mt] += v0 * an0 + v1 * an1;
            psB[mt] += v2 * as0 + v3 * as1;
            pnB[mt] += v2 * an0 + v3 * an1;
            htb[(size_t)c0 * NN + nA]       = __uint_as_float(tf32rn(v0));
            htb[(size_t)(c0 + 1) * NN + nA] = __uint_as_float(tf32rn(v1));
            htb[(size_t)c0 * NN + nB]       = __uint_as_float(tf32rn(v2));
            htb[(size_t)(c0 + 1) * NN + nB] = __uint_as_float(tf32rn(v3));
        }
    }
#pragma unroll
    for (int o = 1; o <= 2; o <<= 1) {
#pragma unroll
        for (int mt = 0; mt < 2; mt++) {
            psA[mt] += __shfl_xor_sync(0xffffffffu, psA[mt], o);
            pnA[mt] += __shfl_xor_sync(0xffffffffu, pnA[mt], o);
            psB[mt] += __shfl_xor_sync(0xffffffffu, psB[mt], o);
            pnB[mt] += __shfl_xor_sync(0xffffffffu, pnB[mt], o);
        }
    }
    if (kq == 0) {
#pragma unroll
        for (int mt = 0; mt < 2; mt++) {
            int rA = warp_m * 32 + mt * 16 + gr;     // true row (ss/sn unpermuted)
            sh_ps[warp_n][rA]     = psA[mt];
            sh_pn[warp_n][rA]     = pnA[mt];
            sh_ps[warp_n][rA + 8] = psB[mt];
            sh_pn[warp_n][rA + 8] = pnB[mt];
        }
    }
    __syncthreads();
    if (tid < 128) {
        g_ss[b * NN + row0 + tid] = sh_ps[0][tid] + sh_ps[1][tid];
        g_sn[b * NN + row0 + tid] = sh_pn[0][tid] + sh_pn[1][tid];
    }
}

// ============================================================================
// Kernel 3: warp-specialized masked-softmax aggregation (tf32 mma.sync).
// 512 threads: warps 0-7 consumers (M32xN64 each), warps 8-15 producers.
// Both A and B in k-permuted PADK-40 layout -> all fragments via LDS.64.
// Consumers preload ALL 4 k-steps' fragments per chunk, then stream 64 MMAs.
// ============================================================================
#define K3_CH 64
#define ST    3
#define STK_BYTES (128*PADK*4)   // 20480 each for A and B
#define ADJ_BYTES (128*32*4)     // 16384
#define OFF_SA   0
#define OFF_SB   (OFF_SA + ST*STK_BYTES)
#define OFF_ADJ  (OFF_SB + ST*STK_BYTES)
#define OFF_F    (OFF_ADJ + ST*ADJ_BYTES)
#define OFF_H    (OFF_F + 2048*4)
#define OFF_EG   (OFF_H + 2048*4)
#define OFF_DEN  (OFF_EG + 128*8)
#define K3_SMEM  (OFF_DEN + 128*4)

__global__ __launch_bounds__(512, 1) void k3_attn(const float* __restrict__ adj,
                                                  float* __restrict__ out) {
    extern __shared__ char dsm[];
    const uint32_t smb = smem_u32(dsm);

    uint32_t* smA   = (uint32_t*)(dsm + OFF_SA);
    uint32_t* smB   = (uint32_t*)(dsm + OFF_SB);
    float*    smAdj = (float*)(dsm + OFF_ADJ);
    float*    shF   = (float*)(dsm + OFF_F);
    float*    shH   = (float*)(dsm + OFF_H);
    float2*   shEG  = (float2*)(dsm + OFF_EG);
    float*    shDen = (float*)(dsm + OFF_DEN);

    const int b    = blockIdx.y;
    const int i0   = blockIdx.x * 128;
    const int tid  = threadIdx.x;
    const int wid  = tid >> 5;
    const int lane = tid & 31;

    const float* adjb = adj + ((size_t)b * NN + i0) * NN;
    const float* htb  = g_ht + (size_t)b * HH * NN;

    const int ptid = tid & 255;
    const int cq   = ptid & 7;
    int crow[4];
#pragma unroll
    for (int p = 0; p < 4; p++) crow[p] = (p * 256 + ptid) >> 3;

    // ---- producer prologue: issue chunks 0,1 ----
    if (wid >= 8) {
#pragma unroll
        for (int c0 = 0; c0 < 2; c0++) {
#pragma unroll
            for (int p = 0; p < 4; p++) {
                int r = crow[p];
                CP_ASYNC16(smb + OFF_ADJ + c0 * ADJ_BYTES + (r * 32 + cq * 4) * 4,
                           adjb + (size_t)r * NN + c0 * 32 + cq * 4);
                CP_ASYNC16(smb + OFF_SB + c0 * STK_BYTES + (r * PADK + cq * 4) * 4,
                           htb + (size_t)r * NN + c0 * 32 + cq * 4);
            }
            CP_COMMIT();
        }
    }

    // ---- tables ----
#pragma unroll
    for (int p = 0; p < 4; p++) {
        int j = p * 512 + tid;
        float sn = g_sn[b * NN + j];
        shF[j] = expf(sn);
        shH[j] = expf(0.2f * sn);
    }
    if (tid < 128) {
        float ss = g_ss[b * NN + i0 + tid];
        shEG[tid] = make_float2(expf(ss), expf(0.2f * ss));
    }
    __syncthreads();

    if (wid >= 8) {
        // ================= PRODUCER =================
        const int pw = wid - 8;
        // permuted store column (pairs (k,k+4) adjacent)
        const int permlane = ((lane >> 3) << 3) + ((lane & 3) << 1) + ((lane >> 2) & 1);
        float den[16];
#pragma unroll
        for (int q = 0; q < 16; q++) den[q] = 0.f;

        for (int g = 0; g < K3_CH; g++) {
            const int s = g % ST;
            if (g < K3_CH - 1) CP_WAIT(1); else CP_WAIT(0);
            BAR_SYNC(PBAR, 256);

            {
                float F = shF[g * 32 + lane];
                float H = shH[g * 32 + lane];
                float*    adjS = smAdj + s * (128 * 32);
                uint32_t* aS   = smA + s * (128 * PADK) + permlane;
#pragma unroll
                for (int ii = 0; ii < 16; ii++) {
                    int    r  = pw * 16 + ii;
                    float  av = adjS[r * 32 + lane];
                    float2 eg = shEG[r];
                    float  pp = eg.x * F;
                    float  w  = av * ((pp >= 1.f) ? pp : eg.y * H);
                    uint32_t wr = tf32rn(w);
                    den[ii] += __uint_as_float(wr);
                    aS[r * PADK] = wr;
                }
            }
            BAR_ARRIVE(FULL0 + s, 512);

            if (g + 2 < K3_CH) {
                const int s2 = (g + 2) % ST;
                if (g >= 1) BAR_SYNC(FREE0 + s2, 512);
                const int j2 = (g + 2) * 32;
#pragma unroll
                for (int p = 0; p < 4; p++) {
                    int r = crow[p];
                    CP_ASYNC16(smb + OFF_ADJ + s2 * ADJ_BYTES + (r * 32 + cq * 4) * 4,
                               adjb + (size_t)r * NN + j2 + cq * 4);
                    CP_ASYNC16(smb + OFF_SB + s2 * STK_BYTES + (r * PADK + cq * 4) * 4,
                               htb + (size_t)r * NN + j2 + cq * 4);
                }
                CP_COMMIT();
            }
        }

#pragma unroll
        for (int ii = 0; ii < 16; ii++) {
            float v = den[ii];
#pragma unroll
            for (int o = 16; o; o >>= 1) v += __shfl_xor_sync(0xffffffffu, v, o);
            if (lane == 0) shDen[pw * 16 + ii] = v;
        }
        __syncthreads();
    } else {
        // ================= CONSUMER (8 warps, M32 x N64) =================
        const int gr     = lane >> 2;
        const int kq     = lane & 3;
        const int warp_m = wid & 3;
        const int warp_n = wid >> 2;

        float acc[2][8][4];
#pragma unroll
        for (int mt = 0; mt < 2; mt++)
#pragma unroll
            for (int nt = 0; nt < 8; nt++)
#pragma unroll
                for (int q = 0; q < 4; q++) acc[mt][nt][q] = 0.f;

        const int arow0 = (warp_m * 32 + gr) * PADK + kq * 2;   // mt=0 lo
        const int brow0 = (warp_n * 64 + gr) * PADK + kq * 2;

        for (int t = 0; t < K3_CH; t++) {
            const int s = t % ST;
            BAR_SYNC(FULL0 + s, 512);
            const uint32_t* sAb = smA + s * (128 * PADK);
            const uint32_t* sBb = smB + s * (128 * PADK);

            // ---- preload ALL fragments for the chunk (LDS.64) ----
            uint2 af[4][2][2];   // [kstep][mt][lo/hi]
            uint2 bf[4][8];      // [kstep][nt]
#pragma unroll
            for (int ks = 0; ks < 4; ks++) {
#pragma unroll
                for (int mt = 0; mt < 2; mt++) {
                    af[ks][mt][0] = *(const uint2*)&sAb[arow0 + mt * 16 * PADK + ks * 8];
                    af[ks][mt][1] = *(const uint2*)&sAb[arow0 + (mt * 16 + 8) * PADK + ks * 8];
                }
#pragma unroll
                for (int nt = 0; nt < 8; nt++)
                    bf[ks][nt] = *(const uint2*)&sBb[brow0 + nt * 8 * PADK + ks * 8];
            }
            // ---- stream 64 MMAs ----
#pragma unroll
            for (int ks = 0; ks < 4; ks++)
#pragma unroll
                for (int mt = 0; mt < 2; mt++)
#pragma unroll
                    for (int nt = 0; nt < 8; nt++)
                        mma_tf32(acc[mt][nt],
                                 af[ks][mt][0].x, af[ks][mt][1].x,
                                 af[ks][mt][0].y, af[ks][mt][1].y,
                                 bf[ks][nt].x, bf[ks][nt].y);

            if (t < K3_CH - ST) BAR_ARRIVE(FREE0 + s, 512);
        }
        __syncthreads();  // shDen ready

        // ---- epilogue ----
#pragma unroll
        for (int mt = 0; mt < 2; mt++) {
            int   rA   = warp_m * 32 + mt * 16 + gr;
            int   rB   = rA + 8;
            float invA = 1.f / shDen[rA];
            float invB = 1.f / shDen[rB];
            float* oA  = out + ((size_t)(b * NN + i0 + rA)) * HH + warp_n * 64;
            float* oB  = out + ((size_t)(b * NN + i0 + rB)) * HH + warp_n * 64;
#pragma unroll
            for (int nt = 0; nt < 8; nt++) {
                float v0 = acc[mt][nt][0] * invA;
                float v1 = acc[mt][nt][1] * invA;
                float v2 = acc[mt][nt][2] * invB;
                float v3 = acc[mt][nt][3] * invB;
                float2 pA, pB;
                pA.x = (v0 > 0.f) ? v0 : expm1f(v0);
                pA.y = (v1 > 0.f) ? v1 : expm1f(v1);
                pB.x = (v2 > 0.f) ? v2 : expm1f(v2);
                pB.y = (v3 > 0.f) ? v3 : expm1f(v3);
                *(float2*)&oA[nt * 8 + kq * 2] = pA;
                *(float2*)&oB[nt * 8 + kq * 2] = pB;
            }
        }
    }
}

// ============================================================================
// Launch
// ============================================================================
extern "C" void kernel_launch(void* const* d_in, const int* in_sizes, int n_in,
                              void* d_out, int out_size) {
    const float* x   = (const float*)d_in[0];  // [8, 2048, 256]
    const float* adj = (const float*)d_in[1];  // [8, 2048, 2048]
    const float* W   = (const float*)d_in[2];  // [128, 256]
    const float* a   = (const float*)d_in[3];  // [256]
    float*       out = (float*)d_out;          // [8, 2048, 128]

    cudaFuncSetAttribute(k3_attn, cudaFuncAttributeMaxDynamicSharedMemorySize,
                         K3_SMEM);

    k1_hgemm<<<dim3(NN / 128, BS), 256>>>(x, W, a);
    k3_attn<<<dim3(NN / 128, BS), 512, K3_SMEM>>>(adj, out);
}

// round 12
// speedup vs baseline: 1.2183x; 1.1388x over previous
#include <cuda_runtime.h>
#include <cstdint>

// Problem constants
#define BS    8
#define NN    2048
#define DIN   256
#define HH    128
#define ALPHA 0.2f

// Scratch (device globals: no allocation allowed)
// g_ht column j is permuted within each 32-group: pos(w)=(w&3)*8+((w>>3)&3)*2+((w>>2)&1)
__device__ float g_ht[BS * HH * NN];
__device__ float g_ss[BS * NN];
__device__ float g_sn[BS * NN];

static __device__ __forceinline__ uint32_t smem_u32(const void* p) {
    uint32_t r;
    asm("{ .reg .u64 t; cvta.to.shared.u64 t, %1; cvt.u32.u64 %0, t; }"
        : "=r"(r) : "l"(p));
    return r;
}

static __device__ __forceinline__ uint32_t tf32rn(float x) {
    uint32_t r;
    asm("cvt.rna.tf32.f32 %0, %1;" : "=r"(r) : "f"(x));
    return r;
}

#define CP_ASYNC16(dst_u32, src_ptr) \
    asm volatile("cp.async.cg.shared.global [%0], [%1], 16;" \
                 :: "r"(dst_u32), "l"(src_ptr) : "memory")
#define CP_COMMIT()  asm volatile("cp.async.commit_group;" ::: "memory")
#define CP_WAIT(n)   asm volatile("cp.async.wait_group %0;" :: "n"(n) : "memory")

#define BAR_SYNC(id, cnt) \
    asm volatile("bar.sync %0, %1;" :: "n"(id), "r"(cnt) : "memory")
#define BAR_ARRIVE(id, cnt) \
    asm volatile("bar.arrive %0, %1;" :: "n"(id), "r"(cnt) : "memory")

// D += A(16x8 row-major) * B(8x8 col-major), tf32 in, fp32 accum
static __device__ __forceinline__ void mma_tf32(float* c, uint32_t a0, uint32_t a1,
                                                uint32_t a2, uint32_t a3,
                                                uint32_t b0, uint32_t b1) {
    asm volatile(
        "mma.sync.aligned.m16n8k8.row.col.f32.tf32.tf32.f32 "
        "{%0,%1,%2,%3}, {%4,%5,%6,%7}, {%8,%9}, {%0,%1,%2,%3};"
        : "+f"(c[0]), "+f"(c[1]), "+f"(c[2]), "+f"(c[3])
        : "r"(a0), "r"(a1), "r"(a2), "r"(a3), "r"(b0), "r"(b1));
}

#define PAD  36  // k1 tile row stride
#define PADK 36  // k3 A/B row stride: conflict-free LDS.128 (banks 4*gr + 8*kq)

// ============================================================================
// Kernel 1: h = x @ W^T on tf32 mma. Epilogue scatters tf32(h) to g_ht with
// the 32-wide k-permutation (consumed by k3 LDS.128 B frags) + ss/sn dots.
// ============================================================================
__global__ __launch_bounds__(256) void k1_hgemm(const float* __restrict__ x,
                                                const float* __restrict__ W,
                                                const float* __restrict__ a) {
    __shared__ uint32_t sA[128][PAD];
    __shared__ uint32_t sB[128][PAD];
    __shared__ float sh_ps[2][128];
    __shared__ float sh_pn[2][128];

    const int b    = blockIdx.y;
    const int row0 = blockIdx.x * 128;
    const int tid  = threadIdx.x;
    const int lane = tid & 31;
    const int gr   = lane >> 2;
    const int kq   = lane & 3;
    const int warp_m = (tid >> 5) & 3;
    const int warp_n = tid >> 7;

    float acc[2][8][4];
#pragma unroll
    for (int mt = 0; mt < 2; mt++)
#pragma unroll
        for (int nt = 0; nt < 8; nt++)
#pragma unroll
            for (int q = 0; q < 4; q++) acc[mt][nt][q] = 0.f;

    const float* xb = x + ((size_t)b * NN + row0) * DIN;

    for (int d0 = 0; d0 < DIN; d0 += 32) {
        __syncthreads();
#pragma unroll
        for (int p = 0; p < 4; p++) {
            int flat = p * 256 + tid;
            int row  = flat >> 3;
            int q8   = flat & 7;
            float4 xv = *(const float4*)(xb + (size_t)row * DIN + d0 + q8 * 4);
            uint4 u;
            u.x = tf32rn(xv.x); u.y = tf32rn(xv.y);
            u.z = tf32rn(xv.z); u.w = tf32rn(xv.w);
            *(uint4*)&sA[row][q8 * 4] = u;
            float4 wv = *(const float4*)(W + (size_t)row * DIN + d0 + q8 * 4);
            u.x = tf32rn(wv.x); u.y = tf32rn(wv.y);
            u.z = tf32rn(wv.z); u.w = tf32rn(wv.w);
            *(uint4*)&sB[row][q8 * 4] = u;
        }
        __syncthreads();

#pragma unroll
        for (int k0 = 0; k0 < 32; k0 += 8) {
            uint32_t afrag[2][4];
#pragma unroll
            for (int mt = 0; mt < 2; mt++) {
                int i = warp_m * 32 + mt * 16 + gr;
                afrag[mt][0] = sA[i][k0 + kq];
                afrag[mt][1] = sA[i + 8][k0 + kq];
                afrag[mt][2] = sA[i][k0 + kq + 4];
                afrag[mt][3] = sA[i + 8][k0 + kq + 4];
            }
            uint32_t bfrag[8][2];
#pragma unroll
            for (int nt = 0; nt < 8; nt++) {
                int n = warp_n * 64 + nt * 8 + gr;
                bfrag[nt][0] = sB[n][k0 + kq];
                bfrag[nt][1] = sB[n][k0 + kq + 4];
            }
#pragma unroll
            for (int mt = 0; mt < 2; mt++)
#pragma unroll
                for (int nt = 0; nt < 8; nt++)
                    mma_tf32(acc[mt][nt], afrag[mt][0], afrag[mt][1],
                             afrag[mt][2], afrag[mt][3],
                             bfrag[nt][0], bfrag[nt][1]);
        }
    }

    // ---- epilogue: scatter h^T (tf32, 32-wide j-permutation) + ss/sn dots ----
    float* htb = g_ht + (size_t)b * HH * NN;
    float psA[2] = {0.f, 0.f}, pnA[2] = {0.f, 0.f};
    float psB[2] = {0.f, 0.f}, pnB[2] = {0.f, 0.f};
#pragma unroll
    for (int mt = 0; mt < 2; mt++) {
        // true within-32 offset w = mt*16 + gr; pos(w) = (gr&3)*8 + 4*mt + (gr>>2)
        int posA = (gr & 3) * 8 + 4 * mt + (gr >> 2);
        int nA   = row0 + warp_m * 32 + posA;
        int nB   = nA + 2;                       // pos(w+8) = pos(w)+2
#pragma unroll
        for (int nt = 0; nt < 8; nt++) {
            int c0 = warp_n * 64 + nt * 8 + kq * 2;
            float as0 = a[c0], as1 = a[c0 + 1];
            float an0 = a[HH + c0], an1 = a[HH + c0 + 1];
            float v0 = acc[mt][nt][0], v1 = acc[mt][nt][1];
            float v2 = acc[mt][nt][2], v3 = acc[mt][nt][3];
            psA[mt] += v0 * as0 + v1 * as1;
            pnA[mt] += v0 * an0 + v1 * an1;
            psB[mt] += v2 * as0 + v3 * as1;
            pnB[mt] += v2 * an0 + v3 * an1;
            htb[(size_t)c0 * NN + nA]       = __uint_as_float(tf32rn(v0));
            htb[(size_t)(c0 + 1) * NN + nA] = __uint_as_float(tf32rn(v1));
            htb[(size_t)c0 * NN + nB]       = __uint_as_float(tf32rn(v2));
            htb[(size_t)(c0 + 1) * NN + nB] = __uint_as_float(tf32rn(v3));
        }
    }
#pragma unroll
    for (int o = 1; o <= 2; o <<= 1) {
#pragma unroll
        for (int mt = 0; mt < 2; mt++) {
            psA[mt] += __shfl_xor_sync(0xffffffffu, psA[mt], o);
            pnA[mt] += __shfl_xor_sync(0xffffffffu, pnA[mt], o);
            psB[mt] += __shfl_xor_sync(0xffffffffu, psB[mt], o);
            pnB[mt] += __shfl_xor_sync(0xffffffffu, pnB[mt], o);
        }
    }
    if (kq == 0) {
#pragma unroll
        for (int mt = 0; mt < 2; mt++) {
            int rA = warp_m * 32 + mt * 16 + gr;     // true rows for ss/sn
            sh_ps[warp_n][rA]     = psA[mt];
            sh_pn[warp_n][rA]     = pnA[mt];
            sh_ps[warp_n][rA + 8] = psB[mt];
            sh_pn[warp_n][rA + 8] = pnB[mt];
        }
    }
    __syncthreads();
    if (tid < 128) {
        g_ss[b * NN + row0 + tid] = sh_ps[0][tid] + sh_ps[1][tid];
        g_sn[b * NN + row0 + tid] = sh_pn[0][tid] + sh_pn[1][tid];
    }
}

// ============================================================================
// Kernel 3: warp-specialized masked-softmax aggregation (tf32 mma.sync).
// 512 threads: 8 consumer warps (M32xN64) + 8 producer warps.
// - adj: direct LDG into registers, prefetched 1 chunk ahead (no smem staging)
// - A/B: k-permuted PADK-36 rows -> all consumer fragments via LDS.128
// - stage-unrolled (x3) loops: compile-time stage -> immediate addressing
// ============================================================================
#define K3_CH 64
#define ST    3
#define STK_WORDS (128*PADK)     // 4608 u32 per stage tile
#define STK_BYTES (STK_WORDS*4)  // 18432
#define OFF_SA   0
#define OFF_SB   (OFF_SA + ST*STK_BYTES)
#define OFF_F    (OFF_SB + ST*STK_BYTES)
#define OFF_H    (OFF_F + 2048*4)
#define OFF_EG   (OFF_H + 2048*4)
#define OFF_DEN  (OFF_EG + 128*8)
#define K3_SMEM  (OFF_DEN + 128*4)

#define FULL0 1
#define FREE0 4

__global__ __launch_bounds__(512, 1) void k3_attn(const float* __restrict__ adj,
                                                  float* __restrict__ out) {
    extern __shared__ char dsm[];
    const uint32_t smb = smem_u32(dsm);

    uint32_t* smA   = (uint32_t*)(dsm + OFF_SA);
    uint32_t* smB   = (uint32_t*)(dsm + OFF_SB);
    float*    shF   = (float*)(dsm + OFF_F);
    float*    shH   = (float*)(dsm + OFF_H);
    float2*   shEG  = (float2*)(dsm + OFF_EG);
    float*    shDen = (float*)(dsm + OFF_DEN);

    const int b    = blockIdx.y;
    const int i0   = blockIdx.x * 128;
    const int tid  = threadIdx.x;
    const int wid  = tid >> 5;
    const int lane = tid & 31;

    const float* adjb = adj + ((size_t)b * NN + i0) * NN;
    const float* htb  = g_ht + (size_t)b * HH * NN;

    // producer cp.async mapping for B (256 producer threads, 1024 16B chunks)
    const int ptid = tid & 255;
    const int cq   = ptid & 7;
    int crow[4];
#pragma unroll
    for (int p = 0; p < 4; p++) crow[p] = (p * 256 + ptid) >> 3;

    // producer adj / gen state
    const int pw = wid - 8;                           // 0..7 when producer
    float adjR[16];

    if (wid >= 8) {
        // prologue: B chunks 0,1 via cp.async; adj chunk 0 via LDG
#pragma unroll
        for (int c0 = 0; c0 < 2; c0++) {
#pragma unroll
            for (int p = 0; p < 4; p++) {
                int r = crow[p];
                CP_ASYNC16(smb + OFF_SB + c0 * STK_BYTES + (r * PADK + cq * 4) * 4,
                           htb + (size_t)r * NN + c0 * 32 + cq * 4);
            }
            CP_COMMIT();
        }
        const float* adjPt = adjb + (size_t)(pw * 16) * NN + lane;
#pragma unroll
        for (int ii = 0; ii < 16; ii++) adjR[ii] = adjPt[(size_t)ii * NN];
    }

    // tables
#pragma unroll
    for (int p = 0; p < 4; p++) {
        int j = p * 512 + tid;
        float sn = g_sn[b * NN + j];
        shF[j] = expf(sn);
        shH[j] = expf(0.2f * sn);
    }
    if (tid < 128) {
        float ss = g_ss[b * NN + i0 + tid];
        shEG[tid] = make_float2(expf(ss), expf(0.2f * ss));
    }
    __syncthreads();

    if (wid >= 8) {
        // ================= PRODUCER =================
        const int poslane = (lane & 3) * 8 + ((lane >> 3) & 3) * 2 + ((lane >> 2) & 1);
        const float* adjPt = adjb + (size_t)(pw * 16) * NN + lane;
        float egx[16], egy[16];
#pragma unroll
        for (int ii = 0; ii < 16; ii++) {
            float2 e = shEG[pw * 16 + ii];
            egx[ii] = e.x; egy[ii] = e.y;
        }
        // REAL C pointers for the A store (generic->shared handled by compiler)
        uint32_t* aPtr[ST];
#pragma unroll
        for (int s = 0; s < ST; s++)
            aPtr[s] = smA + s * STK_WORDS + pw * 16 * PADK + poslane;

        float den[16];
#pragma unroll
        for (int q = 0; q < 16; q++) den[q] = 0.f;

        // one producer chunk; u is compile-time after unroll
#define P_CHUNK(g, u) do {                                                     \
        float F = shF[(g) * 32 + lane];                                        \
        float H = shH[(g) * 32 + lane];                                        \
        _Pragma("unroll")                                                      \
        for (int ii = 0; ii < 16; ii++) {                                      \
            float pp = egx[ii] * F;                                            \
            float qq = egy[ii] * H;                                            \
            float w  = adjR[ii] * ((pp >= 1.f) ? pp : qq);                     \
            uint32_t wr = tf32rn(w);                                           \
            den[ii] += __uint_as_float(wr);                                    \
            aPtr[u][ii * PADK] = wr;                                           \
        }                                                                      \
        if ((g) + 1 < K3_CH) {                                                 \
            _Pragma("unroll")                                                  \
            for (int ii = 0; ii < 16; ii++)                                    \
                adjR[ii] = adjPt[(size_t)ii * NN + ((g) + 1) * 32];            \
        }                                                                      \
        if ((g) == K3_CH - 1) { CP_WAIT(0); } else { CP_WAIT(1); }             \
        BAR_ARRIVE(FULL0 + (u), 512);                                          \
        if ((g) + 2 < K3_CH) {                                                 \
            if ((g) >= 1) BAR_SYNC(FREE0 + ((u) + 2) % ST, 512);               \
            const int j2 = ((g) + 2) * 32;                                     \
            _Pragma("unroll")                                                  \
            for (int p = 0; p < 4; p++) {                                      \
                int r = crow[p];                                               \
                CP_ASYNC16(smb + OFF_SB + (((u) + 2) % ST) * STK_BYTES +       \
                               (r * PADK + cq * 4) * 4,                        \
                           htb + (size_t)r * NN + j2 + cq * 4);                \
            }                                                                  \
            CP_COMMIT();                                                       \
        }                                                                      \
    } while (0)

        for (int t0 = 0; t0 < K3_CH - 1; t0 += 3) {
            P_CHUNK(t0 + 0, 0);
            P_CHUNK(t0 + 1, 1);
            P_CHUNK(t0 + 2, 2);
        }
        P_CHUNK(K3_CH - 1, 0);
#undef P_CHUNK

#pragma unroll
        for (int ii = 0; ii < 16; ii++) {
            float v = den[ii];
#pragma unroll
            for (int o = 16; o; o >>= 1) v += __shfl_xor_sync(0xffffffffu, v, o);
            if (lane == 0) shDen[pw * 16 + ii] = v;
        }
        __syncthreads();
    } else {
        // ================= CONSUMER (8 warps, M32 x N64) =================
        const int gr     = lane >> 2;
        const int kq     = lane & 3;
        const int warp_m = wid & 3;
        const int warp_n = wid >> 2;

        float acc[2][8][4];
#pragma unroll
        for (int mt = 0; mt < 2; mt++)
#pragma unroll
            for (int nt = 0; nt < 8; nt++)
#pragma unroll
                for (int q = 0; q < 4; q++) acc[mt][nt][q] = 0.f;

        const uint32_t* aB[ST];
        const uint32_t* bB[ST];
#pragma unroll
        for (int s = 0; s < ST; s++) {
            aB[s] = smA + s * STK_WORDS + (warp_m * 32 + gr) * PADK + kq * 8;
            bB[s] = smB + s * STK_WORDS + (warp_n * 64 + gr) * PADK + kq * 8;
        }

        // one consumer chunk; u compile-time after unroll
#define C_CHUNK(t, u) do {                                                     \
        BAR_SYNC(FULL0 + (u), 512);                                            \
        const uint32_t* sAu = aB[u];                                           \
        const uint32_t* sBu = bB[u];                                           \
        uint4 aR[4][2];                                                        \
        _Pragma("unroll")                                                      \
        for (int r = 0; r < 4; r++) {                                          \
            aR[r][0] = *(const uint4*)&sAu[r * (8 * PADK)];                    \
            aR[r][1] = *(const uint4*)&sAu[r * (8 * PADK) + 4];                \
        }                                                                      \
        _Pragma("unroll")                                                      \
        for (int np = 0; np < 4; np++) {                                       \
            uint4 bR[2][2];                                                    \
            _Pragma("unroll")                                                  \
            for (int e = 0; e < 2; e++) {                                      \
                bR[e][0] = *(const uint4*)&sBu[(np * 2 + e) * (8 * PADK)];     \
                bR[e][1] = *(const uint4*)&sBu[(np * 2 + e) * (8 * PADK) + 4]; \
            }                                                                  \
            _Pragma("unroll")                                                  \
            for (int ks = 0; ks < 4; ks++) {                                   \
                const int h  = ks >> 1;                                        \
                const int od = ks & 1;                                         \
                _Pragma("unroll")                                              \
                for (int e = 0; e < 2; e++) {                                  \
                    uint32_t b0 = od ? bR[e][h].z : bR[e][h].x;                \
                    uint32_t b1 = od ? bR[e][h].w : bR[e][h].y;                \
                    _Pragma("unroll")                                          \
                    for (int mt = 0; mt < 2; mt++) {                           \
                        uint32_t a0 = od ? aR[2*mt][h].z   : aR[2*mt][h].x;    \
                        uint32_t a1 = od ? aR[2*mt+1][h].z : aR[2*mt+1][h].x;  \
                        uint32_t a2 = od ? aR[2*mt][h].w   : aR[2*mt][h].y;    \
                        uint32_t a3 = od ? aR[2*mt+1][h].w : aR[2*mt+1][h].y;  \
                        mma_tf32(acc[mt][np * 2 + e], a0, a1, a2, a3, b0, b1); \
                    }                                                          \
                }                                                              \
            }                                                                  \
        }                                                                      \
        if ((t) < K3_CH - ST) BAR_ARRIVE(FREE0 + (u), 512);                    \
    } while (0)

        for (int t0 = 0; t0 < K3_CH - 1; t0 += 3) {
            C_CHUNK(t0 + 0, 0);
            C_CHUNK(t0 + 1, 1);
            C_CHUNK(t0 + 2, 2);
        }
        C_CHUNK(K3_CH - 1, 0);
#undef C_CHUNK

        __syncthreads();  // shDen ready

        // ---- epilogue ----
#pragma unroll
        for (int mt = 0; mt < 2; mt++) {
            int   rA   = warp_m * 32 + mt * 16 + gr;
            int   rB   = rA + 8;
            float invA = 1.f / shDen[rA];
            float invB = 1.f / shDen[rB];
            float* oA  = out + ((size_t)(b * NN + i0 + rA)) * HH + warp_n * 64;
            float* oB  = out + ((size_t)(b * NN + i0 + rB)) * HH + warp_n * 64;
#pragma unroll
            for (int nt = 0; nt < 8; nt++) {
                float v0 = acc[mt][nt][0] * invA;
                float v1 = acc[mt][nt][1] * invA;
                float v2 = acc[mt][nt][2] * invB;
                float v3 = acc[mt][nt][3] * invB;
                float2 pA, pB;
                pA.x = (v0 > 0.f) ? v0 : expm1f(v0);
                pA.y = (v1 > 0.f) ? v1 : expm1f(v1);
                pB.x = (v2 > 0.f) ? v2 : expm1f(v2);
                pB.y = (v3 > 0.f) ? v3 : expm1f(v3);
                *(float2*)&oA[nt * 8 + kq * 2] = pA;
                *(float2*)&oB[nt * 8 + kq * 2] = pB;
            }
        }
    }
}

// ============================================================================
// Launch
// ============================================================================
extern "C" void kernel_launch(void* const* d_in, const int* in_sizes, int n_in,
                              void* d_out, int out_size) {
    const float* x   = (const float*)d_in[0];  // [8, 2048, 256]
    const float* adj = (const float*)d_in[1];  // [8, 2048, 2048]
    const float* W   = (const float*)d_in[2];  // [128, 256]
    const float* a   = (const float*)d_in[3];  // [256]
    float*       out = (float*)d_out;          // [8, 2048, 128]

    cudaFuncSetAttribute(k3_attn, cudaFuncAttributeMaxDynamicSharedMemorySize,
                         K3_SMEM);

    k1_hgemm<<<dim3(NN / 128, BS), 256>>>(x, W, a);
    k3_attn<<<dim3(NN / 128, BS), 512, K3_SMEM>>>(adj, out);
}

// round 13
// speedup vs baseline: 1.2625x; 1.0363x over previous
#include <cuda_runtime.h>
#include <cstdint>

// Problem constants
#define BS    8
#define NN    2048
#define DIN   256
#define HH    128
#define ALPHA 0.2f

// Scratch (device globals: no allocation allowed)
// g_ht column j is permuted within each 32-group: pos(w)=(w&3)*8+((w>>3)&3)*2+((w>>2)&1)
__device__ float g_ht[BS * HH * NN];
__device__ float g_ss[BS * NN];
__device__ float g_sn[BS * NN];

static __device__ __forceinline__ uint32_t smem_u32(const void* p) {
    uint32_t r;
    asm("{ .reg .u64 t; cvta.to.shared.u64 t, %1; cvt.u32.u64 %0, t; }"
        : "=r"(r) : "l"(p));
    return r;
}

static __device__ __forceinline__ uint32_t tf32rn(float x) {
    uint32_t r;
    asm("cvt.rna.tf32.f32 %0, %1;" : "=r"(r) : "f"(x));
    return r;
}

#define CP_ASYNC16(dst_u32, src_ptr) \
    asm volatile("cp.async.cg.shared.global [%0], [%1], 16;" \
                 :: "r"(dst_u32), "l"(src_ptr) : "memory")
#define CP_COMMIT()  asm volatile("cp.async.commit_group;" ::: "memory")
#define CP_WAIT(n)   asm volatile("cp.async.wait_group %0;" :: "n"(n) : "memory")

#define BAR_SYNC(id, cnt) \
    asm volatile("bar.sync %0, %1;" :: "n"(id), "r"(cnt) : "memory")
#define BAR_ARRIVE(id, cnt) \
    asm volatile("bar.arrive %0, %1;" :: "n"(id), "r"(cnt) : "memory")

// D += A(16x8 row-major) * B(8x8 col-major), tf32 in, fp32 accum
static __device__ __forceinline__ void mma_tf32(float* c, uint32_t a0, uint32_t a1,
                                                uint32_t a2, uint32_t a3,
                                                uint32_t b0, uint32_t b1) {
    asm volatile(
        "mma.sync.aligned.m16n8k8.row.col.f32.tf32.tf32.f32 "
        "{%0,%1,%2,%3}, {%4,%5,%6,%7}, {%8,%9}, {%0,%1,%2,%3};"
        : "+f"(c[0]), "+f"(c[1]), "+f"(c[2]), "+f"(c[3])
        : "r"(a0), "r"(a1), "r"(a2), "r"(a3), "r"(b0), "r"(b1));
}

#define PAD  36  // k1 tile row stride
#define PADK 36  // k3 A/B row stride: conflict-free LDS.128 (banks 4*gr + 8*kq)

// ============================================================================
// Kernel 1: h = x @ W^T on tf32 mma. Epilogue scatters tf32(h) to g_ht with
// the 32-wide k-permutation (consumed by k3 LDS.128 B frags) + ss/sn dots.
// ============================================================================
__global__ __launch_bounds__(256) void k1_hgemm(const float* __restrict__ x,
                                                const float* __restrict__ W,
                                                const float* __restrict__ a) {
    __shared__ uint32_t sA[128][PAD];
    __shared__ uint32_t sB[128][PAD];
    __shared__ float sh_ps[2][128];
    __shared__ float sh_pn[2][128];

    const int b    = blockIdx.y;
    const int row0 = blockIdx.x * 128;
    const int tid  = threadIdx.x;
    const int lane = tid & 31;
    const int gr   = lane >> 2;
    const int kq   = lane & 3;
    const int warp_m = (tid >> 5) & 3;
    const int warp_n = tid >> 7;

    float acc[2][8][4];
#pragma unroll
    for (int mt = 0; mt < 2; mt++)
#pragma unroll
        for (int nt = 0; nt < 8; nt++)
#pragma unroll
            for (int q = 0; q < 4; q++) acc[mt][nt][q] = 0.f;

    const float* xb = x + ((size_t)b * NN + row0) * DIN;

    for (int d0 = 0; d0 < DIN; d0 += 32) {
        __syncthreads();
#pragma unroll
        for (int p = 0; p < 4; p++) {
            int flat = p * 256 + tid;
            int row  = flat >> 3;
            int q8   = flat & 7;
            float4 xv = *(const float4*)(xb + (size_t)row * DIN + d0 + q8 * 4);
            uint4 u;
            u.x = tf32rn(xv.x); u.y = tf32rn(xv.y);
            u.z = tf32rn(xv.z); u.w = tf32rn(xv.w);
            *(uint4*)&sA[row][q8 * 4] = u;
            float4 wv = *(const float4*)(W + (size_t)row * DIN + d0 + q8 * 4);
            u.x = tf32rn(wv.x); u.y = tf32rn(wv.y);
            u.z = tf32rn(wv.z); u.w = tf32rn(wv.w);
            *(uint4*)&sB[row][q8 * 4] = u;
        }
        __syncthreads();

#pragma unroll
        for (int k0 = 0; k0 < 32; k0 += 8) {
            uint32_t afrag[2][4];
#pragma unroll
            for (int mt = 0; mt < 2; mt++) {
                int i = warp_m * 32 + mt * 16 + gr;
                afrag[mt][0] = sA[i][k0 + kq];
                afrag[mt][1] = sA[i + 8][k0 + kq];
                afrag[mt][2] = sA[i][k0 + kq + 4];
                afrag[mt][3] = sA[i + 8][k0 + kq + 4];
            }
            uint32_t bfrag[8][2];
#pragma unroll
            for (int nt = 0; nt < 8; nt++) {
                int n = warp_n * 64 + nt * 8 + gr;
                bfrag[nt][0] = sB[n][k0 + kq];
                bfrag[nt][1] = sB[n][k0 + kq + 4];
            }
#pragma unroll
            for (int mt = 0; mt < 2; mt++)
#pragma unroll
                for (int nt = 0; nt < 8; nt++)
                    mma_tf32(acc[mt][nt], afrag[mt][0], afrag[mt][1],
                             afrag[mt][2], afrag[mt][3],
                             bfrag[nt][0], bfrag[nt][1]);
        }
    }

    // ---- epilogue: scatter h^T (tf32, 32-wide j-permutation) + ss/sn dots ----
    float* htb = g_ht + (size_t)b * HH * NN;
    float psA[2] = {0.f, 0.f}, pnA[2] = {0.f, 0.f};
    float psB[2] = {0.f, 0.f}, pnB[2] = {0.f, 0.f};
#pragma unroll
    for (int mt = 0; mt < 2; mt++) {
        // true within-32 offset w = mt*16 + gr; pos(w) = (gr&3)*8 + 4*mt + (gr>>2)
        int posA = (gr & 3) * 8 + 4 * mt + (gr >> 2);
        int nA   = row0 + warp_m * 32 + posA;
        int nB   = nA + 2;                       // pos(w+8) = pos(w)+2
#pragma unroll
        for (int nt = 0; nt < 8; nt++) {
            int c0 = warp_n * 64 + nt * 8 + kq * 2;
            float as0 = a[c0], as1 = a[c0 + 1];
            float an0 = a[HH + c0], an1 = a[HH + c0 + 1];
            float v0 = acc[mt][nt][0], v1 = acc[mt][nt][1];
            float v2 = acc[mt][nt][2], v3 = acc[mt][nt][3];
            psA[mt] += v0 * as0 + v1 * as1;
            pnA[mt] += v0 * an0 + v1 * an1;
            psB[mt] += v2 * as0 + v3 * as1;
            pnB[mt] += v2 * an0 + v3 * an1;
            htb[(size_t)c0 * NN + nA]       = __uint_as_float(tf32rn(v0));
            htb[(size_t)(c0 + 1) * NN + nA] = __uint_as_float(tf32rn(v1));
            htb[(size_t)c0 * NN + nB]       = __uint_as_float(tf32rn(v2));
            htb[(size_t)(c0 + 1) * NN + nB] = __uint_as_float(tf32rn(v3));
        }
    }
#pragma unroll
    for (int o = 1; o <= 2; o <<= 1) {
#pragma unroll
        for (int mt = 0; mt < 2; mt++) {
            psA[mt] += __shfl_xor_sync(0xffffffffu, psA[mt], o);
            pnA[mt] += __shfl_xor_sync(0xffffffffu, pnA[mt], o);
            psB[mt] += __shfl_xor_sync(0xffffffffu, psB[mt], o);
            pnB[mt] += __shfl_xor_sync(0xffffffffu, pnB[mt], o);
        }
    }
    if (kq == 0) {
#pragma unroll
        for (int mt = 0; mt < 2; mt++) {
            int rA = warp_m * 32 + mt * 16 + gr;     // true rows for ss/sn
            sh_ps[warp_n][rA]     = psA[mt];
            sh_pn[warp_n][rA]     = pnA[mt];
            sh_ps[warp_n][rA + 8] = psB[mt];
            sh_pn[warp_n][rA + 8] = pnB[mt];
        }
    }
    __syncthreads();
    if (tid < 128) {
        g_ss[b * NN + row0 + tid] = sh_ps[0][tid] + sh_ps[1][tid];
        g_sn[b * NN + row0 + tid] = sh_pn[0][tid] + sh_pn[1][tid];
    }
}

// ============================================================================
// Kernel 3: warp-specialized masked-softmax aggregation (tf32 mma.sync).
// 512 threads: 8 consumer warps (M32xN64) + 8 producer warps.
// - adj: direct LDG into registers, prefetched 1 chunk ahead (no smem staging)
// - A/B: k-permuted PADK-36 rows -> all consumer fragments via LDS.128
// - stage-unrolled (x3): compile-time stage offsets from SINGLE base pointers
// - chunk processed in two k-halves to keep regs < 128 cap (no spills)
// ============================================================================
#define K3_CH 64
#define ST    3
#define STK_WORDS (128*PADK)     // 4608 u32 per stage tile
#define STK_BYTES (STK_WORDS*4)  // 18432
#define OFF_SA   0
#define OFF_SB   (OFF_SA + ST*STK_BYTES)
#define OFF_F    (OFF_SB + ST*STK_BYTES)
#define OFF_H    (OFF_F + 2048*4)
#define OFF_EG   (OFF_H + 2048*4)
#define OFF_DEN  (OFF_EG + 128*8)
#define K3_SMEM  (OFF_DEN + 128*4)

#define FULL0 1
#define FREE0 4

__global__ __launch_bounds__(512, 1) void k3_attn(const float* __restrict__ adj,
                                                  float* __restrict__ out) {
    extern __shared__ char dsm[];
    const uint32_t smb = smem_u32(dsm);

    uint32_t* smA   = (uint32_t*)(dsm + OFF_SA);
    uint32_t* smB   = (uint32_t*)(dsm + OFF_SB);
    float*    shF   = (float*)(dsm + OFF_F);
    float*    shH   = (float*)(dsm + OFF_H);
    float2*   shEG  = (float2*)(dsm + OFF_EG);
    float*    shDen = (float*)(dsm + OFF_DEN);

    const int b    = blockIdx.y;
    const int i0   = blockIdx.x * 128;
    const int tid  = threadIdx.x;
    const int wid  = tid >> 5;
    const int lane = tid & 31;

    const float* adjb = adj + ((size_t)b * NN + i0) * NN;
    const float* htb  = g_ht + (size_t)b * HH * NN;

    // producer cp.async mapping for B (256 producer threads, 1024 16B chunks)
    const int ptid = tid & 255;
    const int cq   = ptid & 7;
    int crow[4];
#pragma unroll
    for (int p = 0; p < 4; p++) crow[p] = (p * 256 + ptid) >> 3;

    // producer adj / gen state
    const int pw = wid - 8;                           // 0..7 when producer
    float adjR[16];

    if (wid >= 8) {
        // prologue: B chunks 0,1 via cp.async; adj chunk 0 via LDG
#pragma unroll
        for (int c0 = 0; c0 < 2; c0++) {
#pragma unroll
            for (int p = 0; p < 4; p++) {
                int r = crow[p];
                CP_ASYNC16(smb + OFF_SB + c0 * STK_BYTES + (r * PADK + cq * 4) * 4,
                           htb + (size_t)r * NN + c0 * 32 + cq * 4);
            }
            CP_COMMIT();
        }
        const float* adjPt = adjb + (size_t)(pw * 16) * NN + lane;
#pragma unroll
        for (int ii = 0; ii < 16; ii++) adjR[ii] = adjPt[(size_t)ii * NN];
    }

    // tables
#pragma unroll
    for (int p = 0; p < 4; p++) {
        int j = p * 512 + tid;
        float sn = g_sn[b * NN + j];
        shF[j] = expf(sn);
        shH[j] = expf(0.2f * sn);
    }
    if (tid < 128) {
        float ss = g_ss[b * NN + i0 + tid];
        shEG[tid] = make_float2(expf(ss), expf(0.2f * ss));
    }
    __syncthreads();

    if (wid >= 8) {
        // ================= PRODUCER =================
        const int poslane = (lane & 3) * 8 + ((lane >> 3) & 3) * 2 + ((lane >> 2) & 1);
        const float* adjPt = adjb + (size_t)(pw * 16) * NN + lane;
        float egx[16], egy[16];
#pragma unroll
        for (int ii = 0; ii < 16; ii++) {
            float2 e = shEG[pw * 16 + ii];
            egx[ii] = e.x; egy[ii] = e.y;
        }
        // single base pointer; stage offset is compile-time (u*STK_WORDS)
        uint32_t* aP = smA + pw * 16 * PADK + poslane;

        float den[16];
#pragma unroll
        for (int q = 0; q < 16; q++) den[q] = 0.f;

        // one producer chunk; u is compile-time after unroll
#define P_CHUNK(g, u) do {                                                     \
        float F = shF[(g) * 32 + lane];                                        \
        float H = shH[(g) * 32 + lane];                                        \
        _Pragma("unroll")                                                      \
        for (int ii = 0; ii < 16; ii++) {                                      \
            float pp = egx[ii] * F;                                            \
            float qq = egy[ii] * H;                                            \
            float w  = adjR[ii] * ((pp >= 1.f) ? pp : qq);                     \
            uint32_t wr = tf32rn(w);                                           \
            den[ii] += __uint_as_float(wr);                                    \
            aP[(u) * STK_WORDS + ii * PADK] = wr;                              \
        }                                                                      \
        if ((g) + 1 < K3_CH) {                                                 \
            _Pragma("unroll")                                                  \
            for (int ii = 0; ii < 16; ii++)                                    \
                adjR[ii] = adjPt[(size_t)ii * NN + ((g) + 1) * 32];            \
        }                                                                      \
        if ((g) == K3_CH - 1) { CP_WAIT(0); } else { CP_WAIT(1); }             \
        BAR_ARRIVE(FULL0 + (u), 512);                                          \
        if ((g) + 2 < K3_CH) {                                                 \
            if ((g) >= 1) BAR_SYNC(FREE0 + ((u) + 2) % ST, 512);               \
            const int j2 = ((g) + 2) * 32;                                     \
            _Pragma("unroll")                                                  \
            for (int p = 0; p < 4; p++) {                                      \
                int r = crow[p];                                               \
                CP_ASYNC16(smb + OFF_SB + (((u) + 2) % ST) * STK_BYTES +       \
                               (r * PADK + cq * 4) * 4,                        \
                           htb + (size_t)r * NN + j2 + cq * 4);                \
            }                                                                  \
            CP_COMMIT();                                                       \
        }                                                                      \
    } while (0)

        for (int t0 = 0; t0 < K3_CH - 1; t0 += 3) {
            P_CHUNK(t0 + 0, 0);
            P_CHUNK(t0 + 1, 1);
            P_CHUNK(t0 + 2, 2);
        }
        P_CHUNK(K3_CH - 1, 0);
#undef P_CHUNK

#pragma unroll
        for (int ii = 0; ii < 16; ii++) {
            float v = den[ii];
#pragma unroll
            for (int o = 16; o; o >>= 1) v += __shfl_xor_sync(0xffffffffu, v, o);
            if (lane == 0) shDen[pw * 16 + ii] = v;
        }
        __syncthreads();
    } else {
        // ================= CONSUMER (8 warps, M32 x N64) =================
        const int gr     = lane >> 2;
        const int kq     = lane & 3;
        const int warp_m = wid & 3;
        const int warp_n = wid >> 2;

        float acc[2][8][4];
#pragma unroll
        for (int mt = 0; mt < 2; mt++)
#pragma unroll
            for (int nt = 0; nt < 8; nt++)
#pragma unroll
                for (int q = 0; q < 4; q++) acc[mt][nt][q] = 0.f;

        // single base pointers; stage offsets compile-time
        const uint32_t* aB0 = smA + (warp_m * 32 + gr) * PADK + kq * 8;
        const uint32_t* bB0 = smB + (warp_n * 64 + gr) * PADK + kq * 8;

        // one consumer chunk; u compile-time after unroll.
        // Two k-halves (h): each loads A 4x uint4 + per-np B 2x uint4,
        // keeping transient regs ~24 (vs 48) -> total < 128, no spills.
#define C_CHUNK(t, u) do {                                                     \
        BAR_SYNC(FULL0 + (u), 512);                                            \
        const uint32_t* sAu = aB0 + (u) * STK_WORDS;                           \
        const uint32_t* sBu = bB0 + (u) * STK_WORDS;                           \
        _Pragma("unroll")                                                      \
        for (int h = 0; h < 2; h++) {                                          \
            uint4 aRh[4];                                                      \
            _Pragma("unroll")                                                  \
            for (int r = 0; r < 4; r++)                                        \
                aRh[r] = *(const uint4*)&sAu[r * (8 * PADK) + 4 * h];          \
            _Pragma("unroll")                                                  \
            for (int np = 0; np < 4; np++) {                                   \
                uint4 bRh[2];                                                  \
                _Pragma("unroll")                                              \
                for (int e = 0; e < 2; e++)                                    \
                    bRh[e] = *(const uint4*)&sBu[(np * 2 + e) * (8 * PADK) + 4 * h]; \
                _Pragma("unroll")                                              \
                for (int od = 0; od < 2; od++) {                               \
                    _Pragma("unroll")                                          \
                    for (int e = 0; e < 2; e++) {                              \
                        uint32_t b0 = od ? bRh[e].z : bRh[e].x;                \
                        uint32_t b1 = od ? bRh[e].w : bRh[e].y;                \
                        _Pragma("unroll")                                      \
                        for (int mt = 0; mt < 2; mt++) {                       \
                            uint32_t a0 = od ? aRh[2*mt].z   : aRh[2*mt].x;    \
                            uint32_t a1 = od ? aRh[2*mt+1].z : aRh[2*mt+1].x;  \
                            uint32_t a2 = od ? aRh[2*mt].w   : aRh[2*mt].y;    \
                            uint32_t a3 = od ? aRh[2*mt+1].w : aRh[2*mt+1].y;  \
                            mma_tf32(acc[mt][np * 2 + e], a0, a1, a2, a3, b0, b1); \
                        }                                                      \
                    }                                                          \
                }                                                              \
            }                                                                  \
        }                                                                      \
        if ((t) < K3_CH - ST) BAR_ARRIVE(FREE0 + (u), 512);                    \
    } while (0)

        for (int t0 = 0; t0 < K3_CH - 1; t0 += 3) {
            C_CHUNK(t0 + 0, 0);
            C_CHUNK(t0 + 1, 1);
            C_CHUNK(t0 + 2, 2);
        }
        C_CHUNK(K3_CH - 1, 0);
#undef C_CHUNK

        __syncthreads();  // shDen ready

        // ---- epilogue ----
#pragma unroll
        for (int mt = 0; mt < 2; mt++) {
            int   rA   = warp_m * 32 + mt * 16 + gr;
            int   rB   = rA + 8;
            float invA = 1.f / shDen[rA];
            float invB = 1.f / shDen[rB];
            float* oA  = out + ((size_t)(b * NN + i0 + rA)) * HH + warp_n * 64;
            float* oB  = out + ((size_t)(b * NN + i0 + rB)) * HH + warp_n * 64;
#pragma unroll
            for (int nt = 0; nt < 8; nt++) {
                float v0 = acc[mt][nt][0] * invA;
                float v1 = acc[mt][nt][1] * invA;
                float v2 = acc[mt][nt][2] * invB;
                float v3 = acc[mt][nt][3] * invB;
                float2 pA, pB;
                pA.x = (v0 > 0.f) ? v0 : expm1f(v0);
                pA.y = (v1 > 0.f) ? v1 : expm1f(v1);
                pB.x = (v2 > 0.f) ? v2 : expm1f(v2);
                pB.y = (v3 > 0.f) ? v3 : expm1f(v3);
                *(float2*)&oA[nt * 8 + kq * 2] = pA;
                *(float2*)&oB[nt * 8 + kq * 2] = pB;
            }
        }
    }
}

// ============================================================================
// Launch
// ============================================================================
extern "C" void kernel_launch(void* const* d_in, const int* in_sizes, int n_in,
                              void* d_out, int out_size) {
    const float* x   = (const float*)d_in[0];  // [8, 2048, 256]
    const float* adj = (const float*)d_in[1];  // [8, 2048, 2048]
    const float* W   = (const float*)d_in[2];  // [128, 256]
    const float* a   = (const float*)d_in[3];  // [256]
    float*       out = (float*)d_out;          // [8, 2048, 128]

    cudaFuncSetAttribute(k3_attn, cudaFuncAttributeMaxDynamicSharedMemorySize,
                         K3_SMEM);

    k1_hgemm<<<dim3(NN / 128, BS), 256>>>(x, W, a);
    k3_attn<<<dim3(NN / 128, BS), 512, K3_SMEM>>>(adj, out);
}